// round 15
// baseline (speedup 1.0000x reference)
#include <cuda_runtime.h>
#include <cstdint>

#define BATCH   32
#define NA      9
#define HW      4096
#define NPROP   (HW*NA)          // 36864
#define NVEC    (NPROP/4)        // 9216 float4 per batch
#define TOPK    300
#define OUTC    66
#define CAP     2048
#define LCAP    1024             // per-CTA staging (expect ~115)
#define SLICES  4                // topk compact CTAs per batch
#define NCTA    592              // EXACTLY one wave at 4 CTA/SM on 148 SMs
#define NITEMS  1216             // 38 groups x 32 batches

// key threshold for score >= 2.25f (~450 candidates/batch expected, 7σ > 300)
#define THR_FAST 0xC0100000u

// Anchor (w,h) table; centers are always (8+16*gx, 8+16*gy)
__constant__ float c_aw[9] = {92.f,184.f,368.f,64.f,128.f,256.f,44.f,88.f,176.f};
__constant__ float c_ah[9] = {48.f,96.f,192.f,64.f,128.f,256.f,88.f,176.f,352.f};

__device__ int                g_cnt[BATCH * 32];   // candidate counts (128B apart)
__device__ int                g_done[BATCH * 32];  // topk slice tickets
__device__ int                g_dcnt[BATCH * 32];  // decode completion tickets
__device__ int                g_ready[BATCH];      // per-batch ready flags
__device__ unsigned long long g_cand[BATCH * CAP];
__device__ unsigned           g_dec[BATCH * TOPK]; // n | (rank<<16), asc n

__device__ __forceinline__ unsigned f2key(float s) {
    unsigned u = __float_as_uint(s);
    return (u & 0x80000000u) ? ~u : (u | 0x80000000u);
}

// ---------------------------------------------------------------------------
// ONE kernel, ONE wave (592 CTAs x 512 thr, 4/SM). CTAs 0..127 first run
// compact + elected rank for their batch, then ALL CTAs stream 1216 decode
// items, spin-waiting per item on that batch's ready flag. All CTAs are
// resident from t=0, so spins are deadlock-free and block nothing behind.
// ---------------------------------------------------------------------------
__global__ __launch_bounds__(512, 4)
void fused_kernel(const float* __restrict__ scores_in,
                  const float* __restrict__ bbox,
                  const float* __restrict__ im_info,
                  float* __restrict__ out)
{
    __shared__ unsigned long long buf[LCAP];       // 8 KB  (compact staging)
    __shared__ unsigned long long cand[CAP + 16];  // 16.1 KB (rank, padded)
    __shared__ unsigned hist[4096];                // 16 KB (fallback only)
    __shared__ unsigned sel_n[TOPK + 8];           // padded for unroll
    __shared__ unsigned wsum[16], wpre[16];
    __shared__ unsigned s_thr;
    __shared__ int s_cnt, s_base, s_C, s_isrank;

    const int c   = blockIdx.x;
    const int tid = threadIdx.x;
    const unsigned lane = tid & 31u;
    const int warp = tid >> 5;

    // ===================== Phase A: topk (CTAs 0..127) =====================
    if (c < SLICES * BATCH) {
        const int b     = c >> 2;
        const int slice = c & 3;
        const float4* sp =
            (const float4*)(scores_in + (size_t)b * 18 * HW + (size_t)NA * HW);

        // ---- compact: smem staging, one global RMW ----
        if (tid == 0) s_cnt = 0;
        __syncthreads();

        for (int i = slice * 512 + tid; i < NVEC; i += SLICES * 512) {
            float4 v = sp[i];
            float vv[4] = {v.x, v.y, v.z, v.w};
            #pragma unroll
            for (int j = 0; j < 4; j++) {
                unsigned k = f2key(vv[j]);
                if (k >= THR_FAST) {
                    int idx = 4 * i + j;            // memory order: a*4096 + hw
                    int a = idx >> 12, hw = idx & 4095;
                    int n = hw * 9 + a;             // jax flat order
                    int pos = atomicAdd(&s_cnt, 1); // smem atomic: cheap
                    if (pos < LCAP)
                        buf[pos] = ((unsigned long long)k << 32) | (unsigned)(~n);
                }
            }
        }
        __syncthreads();

        const int cnt = s_cnt;
        if (cnt > LCAP) {
            // staging overflow (benign-impossible): poison -> exact fallback
            if (tid == 0) atomicAdd(&g_cnt[b * 32], CAP + 1);
        } else {
            if (tid == 0) s_base = atomicAdd(&g_cnt[b * 32], cnt);  // ONE RMW
            __syncthreads();
            for (int i = tid; i < cnt; i += 512) {
                int pos = s_base + i;
                if (pos < CAP) g_cand[b * CAP + pos] = buf[i];
            }
        }
        __threadfence();                  // publish candidate writes
        __syncthreads();
        if (tid == 0) {
            int t = atomicAdd(&g_done[b * 32], 1);
            s_isrank = (t == SLICES - 1); // last finisher ranks this batch
        }
        __syncthreads();

        if (s_isrank) {
            // ---- rank (elected CTA; all peers already done) ----
            __threadfence();              // acquire peers' g_cand writes
            if (tid == 0) s_C = g_cnt[b * 32];
            __syncthreads();
            int C = s_C;
            if (tid == 0) { g_cnt[b * 32] = 0; g_done[b * 32] = 0; } // replay reset

            if (C >= TOPK && C <= CAP) {
                for (int i = tid; i < C; i += 512)
                    cand[i] = g_cand[b * CAP + i];
            } else {
                // ---- exact fallback: 4096-bin histogram select (512 thr) ----
                #pragma unroll
                for (int i = tid; i < 4096; i += 512) hist[i] = 0;
                if (tid == 0) s_cnt = 0;
                __syncthreads();
                for (int i = tid; i < NVEC; i += 512) {
                    float4 v = sp[i];
                    atomicAdd(&hist[f2key(v.x) >> 20], 1u);
                    atomicAdd(&hist[f2key(v.y) >> 20], 1u);
                    atomicAdd(&hist[f2key(v.z) >> 20], 1u);
                    atomicAdd(&hist[f2key(v.w) >> 20], 1u);
                }
                __syncthreads();
                // suffix scan: thread t owns bins [4095-8t .. 4088-8t]
                const int bhi = 4095 - 8 * tid;
                unsigned hh[8];
                unsigned s = 0;
                #pragma unroll
                for (int j = 0; j < 8; j++) { hh[j] = hist[bhi - j]; s += hh[j]; }
                unsigned incl = s;
                #pragma unroll
                for (int o = 1; o < 32; o <<= 1) {
                    unsigned v = __shfl_up_sync(0xFFFFFFFFu, incl, o);
                    if (lane >= o) incl += v;
                }
                if (lane == 31) wsum[warp] = incl;
                __syncthreads();
                if (warp == 0 && lane < 16) {
                    unsigned w = wsum[lane];
                    unsigned wi = w;
                    #pragma unroll
                    for (int o = 1; o < 16; o <<= 1) {
                        unsigned v = __shfl_up_sync(0xFFFFu, wi, o);
                        if (lane >= o) wi += v;
                    }
                    wpre[lane] = wi - w;
                }
                __syncthreads();
                {
                    unsigned cc = wpre[warp] + (incl - s);   // above bin bhi
                    #pragma unroll
                    for (int j = 0; j < 8; j++) {
                        if (cc < TOPK && cc + hh[j] >= TOPK)
                            s_thr = ((unsigned)(bhi - j)) << 20;
                        cc += hh[j];
                    }
                }
                __syncthreads();
                const unsigned thr = s_thr;
                if (tid == 0) s_cnt = 0;
                __syncthreads();
                for (int i = tid; i < NVEC; i += 512) {
                    float4 v = sp[i];
                    float vv[4] = {v.x, v.y, v.z, v.w};
                    #pragma unroll
                    for (int j = 0; j < 4; j++) {
                        unsigned k = f2key(vv[j]);
                        if (k >= thr) {
                            int idx = 4 * i + j;
                            int a = idx >> 12, hw = idx & 4095;
                            int n = hw * 9 + a;
                            int pos = atomicAdd(&s_cnt, 1);
                            if (pos < CAP)
                                cand[pos] = ((unsigned long long)k << 32)
                                            | (unsigned)(~n);
                        }
                    }
                }
                __syncthreads();
                C = min(s_cnt, CAP);
            }
            // zero-pad so the unrolled rank loop can overrun harmlessly
            if (tid < 16) cand[C + tid] = 0ull;
            __syncthreads();

            // exact rank by counting, 16x unrolled (independent LDS in flight)
            for (int i = tid; i < C; i += 512) {
                const unsigned long long me = cand[i];
                int r = 0;
                for (int j = 0; j < C; j += 16) {
                    #pragma unroll
                    for (int u = 0; u < 16; u++)
                        r += (cand[j + u] > me);
                }
                if (r < TOPK) {
                    unsigned n = (unsigned)(~(unsigned)me);
                    sel_n[r] = n;
                    unsigned k32 = (unsigned)(me >> 32);
                    unsigned u = (k32 & 0x80000000u) ? (k32 & 0x7FFFFFFFu) : ~k32;
                    size_t row = ((size_t)b * TOPK + r) * OUTC;
                    out[row + 0] = (float)b;
                    out[row + OUTC - 1] = __uint_as_float(u);
                }
            }
            if (tid < 8) sel_n[TOPK + tid] = 0xFFFFFFFFu;  // pad
            __syncthreads();

            // decode feed in ascending flat-index order (gather locality)
            if (tid < TOPK) {
                unsigned n = sel_n[tid];
                int o = 0;
                for (int j = 0; j < TOPK + 4; j += 4) {
                    #pragma unroll
                    for (int u = 0; u < 4; u++)
                        o += (sel_n[j + u] < n);
                }
                g_dec[b * TOPK + o] = n | ((unsigned)tid << 16);
            }
            __threadfence();              // publish g_dec + out before flag
            __syncthreads();
            if (tid == 0) atomicExch(&g_ready[b], 1);
        }
    }

    // ============ Phase B: decode work-item loop (ALL 592 CTAs) ============
    const int k    = tid & 63;
    const int gsub = tid >> 6;            // 0..7: proposal slot within item
    const unsigned base = (tid & 31u) & ~3u;

    for (int it = c; it < NITEMS; it += NCTA) {
        const int bd  = it & 31;          // batch
        const int grp = it >> 5;          // proposal group 0..37
        const int jj  = grp * 8 + gsub;   // rank-slot (uniform per 64-group)

        if (tid == 0) {
            while (((volatile int*)g_ready)[bd] == 0) __nanosleep(64);
        }
        __syncthreads();
        __threadfence();                  // acquire producer writes

        if (jj < TOPK) {
            const unsigned packed = g_dec[bd * TOPK + jj];
            const int n    = packed & 0xFFFFu;
            const int rank = packed >> 16;

            const int a  = n % 9;
            const int hw = n / 9;
            const float w  = c_aw[a];
            const float h  = c_ah[a];
            const float cx = 8.0f + 16.0f * (float)(hw & 63);
            const float cy = 8.0f + 16.0f * (float)(hw >> 6);

            const float d =
                __ldcs(&bbox[((size_t)bd * 576 + (size_t)a * 64 + k) * HW + hw]);

            const float d0 = __shfl_sync(0xFFFFFFFFu, d, base + 0);
            const float d1 = __shfl_sync(0xFFFFFFFFu, d, base + 1);
            const float d2 = __shfl_sync(0xFFFFFFFFu, d, base + 2);
            const float d3 = __shfl_sync(0xFFFFFFFFu, d, base + 3);

            const float xmax = im_info[bd * 3 + 1] - 1.0f;
            const float ymax = im_info[bd * 3 + 0] - 1.0f;

            const float pcx = d0 * w + cx;
            const float pcy = d1 * h + cy;
            const float pw  = expf(d2) * w;
            const float ph  = expf(d3) * h;

            float v;
            switch (k & 3) {
                case 0: v = fminf(fmaxf(pcx - 0.5f * pw, 0.0f), xmax); break;
                case 1: v = fminf(fmaxf(pcy - 0.5f * ph, 0.0f), ymax); break;
                case 2: v = fminf(fmaxf(pcx + 0.5f * pw, 0.0f), xmax); break;
                default: v = fminf(fmaxf(pcy + 0.5f * ph, 0.0f), ymax); break;
            }

            out[((size_t)bd * TOPK + rank) * OUTC + 1 + k] = v;
        }

        // replay reset: last item of each batch clears that batch's flag
        __syncthreads();
        if (tid == 0) {
            int t = atomicAdd(&g_dcnt[bd * 32], 1);
            if (t == (NITEMS / BATCH) - 1) {   // 38th item of this batch
                g_dcnt[bd * 32] = 0;
                ((volatile int*)g_ready)[bd] = 0;
            }
        }
    }
}

extern "C" void kernel_launch(void* const* d_in, const int* in_sizes, int n_in,
                              void* d_out, int out_size)
{
    const float* scores  = (const float*)d_in[0];  // (32,18,64,64)
    const float* bbox    = (const float*)d_in[1];  // (32,576,64,64)
    const float* im_info = (const float*)d_in[2];  // (32,3)
    float* out = (float*)d_out;                    // (32,300,66)

    fused_kernel<<<NCTA, 512>>>(scores, bbox, im_info, out);
}

// round 16
// speedup vs baseline: 1.3274x; 1.3274x over previous
#include <cuda_runtime.h>
#include <cstdint>

#define BATCH   32
#define NA      9
#define HW      4096
#define NPROP   (HW*NA)          // 36864
#define NVEC    (NPROP/4)        // 9216 float4 per batch
#define TOPK    300
#define OUTC    66
#define CAP     2048
#define LCAP    1024             // per-CTA staging (expect ~115)
#define SLICES  4                // compact CTAs per batch
#define DGRP    38               // decode CTAs per batch (ceil(300/8))

// key threshold for score >= 2.25f (~450 candidates/batch expected, 7σ > 300)
#define THR_FAST 0xC0100000u

// Anchor (w,h) table; centers are always (8+16*gx, 8+16*gy)
__constant__ float c_aw[9] = {92.f,184.f,368.f,64.f,128.f,256.f,44.f,88.f,176.f};
__constant__ float c_ah[9] = {48.f,96.f,192.f,64.f,128.f,256.f,88.f,176.f,352.f};

__device__ int                g_cnt[BATCH * 32];   // candidate counts (128B apart)
__device__ int                g_done[BATCH * 32];  // topk slice tickets
__device__ int                g_dcnt[BATCH * 32];  // decode completion tickets
__device__ int                g_ready[BATCH];      // per-batch ready flags
__device__ unsigned long long g_cand[BATCH * CAP];
__device__ unsigned           g_dec[BATCH * TOPK]; // n | (rank<<16), asc n

__device__ __forceinline__ unsigned f2key(float s) {
    unsigned u = __float_as_uint(s);
    return (u & 0x80000000u) ? ~u : (u | 0x80000000u);
}

// ---------------------------------------------------------------------------
// Kernel 1 (primary): compact + elected-last-finisher rank. R12-proven.
// Triggers the dependent decode launch as soon as compaction is published.
// ---------------------------------------------------------------------------
__global__ __launch_bounds__(1024, 1)
void topk_kernel(const float* __restrict__ scores_in, float* __restrict__ out)
{
    __shared__ unsigned long long buf[LCAP];       // 8 KB  (compact staging)
    __shared__ unsigned long long cand[CAP + 16];  // 16.1 KB (rank, padded)
    __shared__ unsigned hist[4096];                // 16 KB (fallback only)
    __shared__ unsigned sel_n[TOPK + 8];           // padded for unroll
    __shared__ unsigned wsum[32], wpre[32];
    __shared__ unsigned s_thr;
    __shared__ int s_cnt, s_base, s_C, s_isrank;

    const int b     = blockIdx.y;
    const int slice = blockIdx.x;
    const int tid   = threadIdx.x;
    const unsigned lane = tid & 31u;
    const int warp  = tid >> 5;

    const float4* sp =
        (const float4*)(scores_in + (size_t)b * 18 * HW + (size_t)NA * HW);

    // ---------------- compact: smem staging, one global RMW ----------------
    if (tid == 0) s_cnt = 0;
    __syncthreads();

    for (int i = slice * 1024 + tid; i < NVEC; i += SLICES * 1024) {
        float4 v = sp[i];
        float vv[4] = {v.x, v.y, v.z, v.w};
        #pragma unroll
        for (int j = 0; j < 4; j++) {
            unsigned k = f2key(vv[j]);
            if (k >= THR_FAST) {
                int idx = 4 * i + j;               // memory order: a*4096 + hw
                int a = idx >> 12, hw = idx & 4095;
                int n = hw * 9 + a;                // jax flat order
                int pos = atomicAdd(&s_cnt, 1);    // smem atomic: cheap
                if (pos < LCAP)
                    buf[pos] = ((unsigned long long)k << 32) | (unsigned)(~n);
            }
        }
    }
    __syncthreads();

    const int cnt = s_cnt;
    if (cnt > LCAP) {
        // staging overflow (benign-impossible): poison count -> exact fallback
        if (tid == 0) atomicAdd(&g_cnt[b * 32], CAP + 1);
    } else {
        if (tid == 0) s_base = atomicAdd(&g_cnt[b * 32], cnt);  // ONE RMW
        __syncthreads();
        for (int i = tid; i < cnt; i += 1024) {
            int pos = s_base + i;
            if (pos < CAP) g_cand[b * CAP + pos] = buf[i];
        }
    }
    __threadfence();                  // publish this CTA's candidate writes
    __syncthreads();
    if (tid == 0) {
        int t = atomicAdd(&g_done[b * 32], 1);
        s_isrank = (t == SLICES - 1); // last finisher ranks this batch
    }
    // Allow the dependent decode kernel to start launching NOW
    // (decode CTAs will spin on per-batch g_ready flags).
    asm volatile("griddepcontrol.launch_dependents;" ::: "memory");
    __syncthreads();
    if (!s_isrank) return;

    // ---------------- rank (elected CTA; all peers already done) ----------
    __threadfence();                  // acquire peers' g_cand writes
    if (tid == 0) s_C = g_cnt[b * 32];
    __syncthreads();
    int C = s_C;
    if (tid == 0) { g_cnt[b * 32] = 0; g_done[b * 32] = 0; }   // replay reset

    if (C >= TOPK && C <= CAP) {
        for (int i = tid; i < C; i += 1024)
            cand[i] = g_cand[b * CAP + i];
    } else {
        // ---- exact fallback: 4096-bin histogram select (1024 threads) ----
        #pragma unroll
        for (int i = tid; i < 4096; i += 1024) hist[i] = 0;
        if (tid == 0) s_cnt = 0;
        __syncthreads();
        #pragma unroll 3
        for (int i = tid; i < NVEC; i += 1024) {
            float4 v = sp[i];
            atomicAdd(&hist[f2key(v.x) >> 20], 1u);
            atomicAdd(&hist[f2key(v.y) >> 20], 1u);
            atomicAdd(&hist[f2key(v.z) >> 20], 1u);
            atomicAdd(&hist[f2key(v.w) >> 20], 1u);
        }
        __syncthreads();
        // suffix scan from the top: thread t owns bins [4095-4t .. 4092-4t]
        const int bhi = 4095 - 4 * tid;
        unsigned h0 = hist[bhi],     h1 = hist[bhi - 1];
        unsigned h2 = hist[bhi - 2], h3 = hist[bhi - 3];
        unsigned s = h0 + h1 + h2 + h3;
        unsigned incl = s;
        #pragma unroll
        for (int o = 1; o < 32; o <<= 1) {
            unsigned v = __shfl_up_sync(0xFFFFFFFFu, incl, o);
            if (lane >= o) incl += v;
        }
        if (lane == 31) wsum[warp] = incl;
        __syncthreads();
        if (warp == 0) {
            unsigned w = wsum[lane];
            unsigned wi = w;
            #pragma unroll
            for (int o = 1; o < 32; o <<= 1) {
                unsigned v = __shfl_up_sync(0xFFFFFFFFu, wi, o);
                if (lane >= o) wi += v;
            }
            wpre[lane] = wi - w;
        }
        __syncthreads();
        {
            unsigned cc = wpre[warp] + (incl - s);   // count above bin bhi
            unsigned hh[4] = {h0, h1, h2, h3};
            #pragma unroll
            for (int j = 0; j < 4; j++) {
                if (cc < TOPK && cc + hh[j] >= TOPK)
                    s_thr = ((unsigned)(bhi - j)) << 20;
                cc += hh[j];
            }
        }
        __syncthreads();
        const unsigned thr = s_thr;
        if (tid == 0) s_cnt = 0;
        __syncthreads();
        #pragma unroll 3
        for (int i = tid; i < NVEC; i += 1024) {
            float4 v = sp[i];
            float vv[4] = {v.x, v.y, v.z, v.w};
            #pragma unroll
            for (int j = 0; j < 4; j++) {
                unsigned k = f2key(vv[j]);
                if (k >= thr) {
                    int idx = 4 * i + j;
                    int a = idx >> 12, hw = idx & 4095;
                    int n = hw * 9 + a;
                    int pos = atomicAdd(&s_cnt, 1);
                    if (pos < CAP)
                        cand[pos] = ((unsigned long long)k << 32) | (unsigned)(~n);
                }
            }
        }
        __syncthreads();
        C = min(s_cnt, CAP);
    }
    // zero-pad so the unrolled rank loop can overrun harmlessly
    if (tid < 16) cand[C + tid] = 0ull;
    __syncthreads();

    // ---- exact rank by counting, 16x unrolled (independent LDS in flight)
    for (int i = tid; i < C; i += 1024) {
        const unsigned long long me = cand[i];
        int r = 0;
        for (int j = 0; j < C; j += 16) {
            #pragma unroll
            for (int u = 0; u < 16; u++)
                r += (cand[j + u] > me);           // broadcast reads
        }
        if (r < TOPK) {
            unsigned n = (unsigned)(~(unsigned)me);
            sel_n[r] = n;
            unsigned k32 = (unsigned)(me >> 32);
            unsigned u = (k32 & 0x80000000u) ? (k32 & 0x7FFFFFFFu) : ~k32;
            size_t row = ((size_t)b * TOPK + r) * OUTC;
            out[row + 0] = (float)b;
            out[row + OUTC - 1] = __uint_as_float(u);
        }
    }
    if (tid < 8) sel_n[TOPK + tid] = 0xFFFFFFFFu;  // pad: never counts as less
    __syncthreads();

    // decode feed in ascending flat-index order (gather locality), unrolled
    if (tid < TOPK) {
        unsigned n = sel_n[tid];
        int o = 0;
        for (int j = 0; j < TOPK + 4; j += 4) {
            #pragma unroll
            for (int u = 0; u < 4; u++)
                o += (sel_n[j + u] < n);
        }
        g_dec[b * TOPK + o] = n | ((unsigned)tid << 16);
    }
    __threadfence();                  // publish g_dec + out before flag
    __syncthreads();
    if (tid == 0) atomicExch(&g_ready[b], 1);   // release this batch
}

// ---------------------------------------------------------------------------
// Kernel 2 (PDL secondary): decode — R12-proven body + per-batch flag wait.
// ---------------------------------------------------------------------------
__global__ __launch_bounds__(512)
void decode_kernel(const float* __restrict__ bbox,
                   const float* __restrict__ im_info,
                   float* __restrict__ out)
{
    const int tid = threadIdx.x;
    const int j = blockIdx.x * 8 + (tid >> 6);
    const int b = blockIdx.y;
    const int k = tid & 63;

    // Wait for this batch's topk to be published (acquire via flag+fence).
    if (tid == 0) {
        while (((volatile int*)g_ready)[b] == 0) __nanosleep(64);
    }
    __syncthreads();
    __threadfence();

    if (j < TOPK) {
        const unsigned packed = g_dec[b * TOPK + j];
        const int n    = packed & 0xFFFFu;
        const int rank = packed >> 16;

        const int a  = n % 9;
        const int hw = n / 9;
        const float w  = c_aw[a];
        const float h  = c_ah[a];
        const float cx = 8.0f + 16.0f * (float)(hw & 63);
        const float cy = 8.0f + 16.0f * (float)(hw >> 6);

        const float d =
            __ldcs(&bbox[((size_t)b * 576 + (size_t)a * 64 + k) * HW + hw]);

        const unsigned base = (tid & 31u) & ~3u;
        const float d0 = __shfl_sync(0xFFFFFFFFu, d, base + 0);
        const float d1 = __shfl_sync(0xFFFFFFFFu, d, base + 1);
        const float d2 = __shfl_sync(0xFFFFFFFFu, d, base + 2);
        const float d3 = __shfl_sync(0xFFFFFFFFu, d, base + 3);

        const float xmax = im_info[b * 3 + 1] - 1.0f;
        const float ymax = im_info[b * 3 + 0] - 1.0f;

        const float pcx = d0 * w + cx;
        const float pcy = d1 * h + cy;
        const float pw  = expf(d2) * w;
        const float ph  = expf(d3) * h;

        float v;
        switch (k & 3) {
            case 0: v = fminf(fmaxf(pcx - 0.5f * pw, 0.0f), xmax); break;
            case 1: v = fminf(fmaxf(pcy - 0.5f * ph, 0.0f), ymax); break;
            case 2: v = fminf(fmaxf(pcx + 0.5f * pw, 0.0f), xmax); break;
            default: v = fminf(fmaxf(pcy + 0.5f * ph, 0.0f), ymax); break;
        }

        out[((size_t)b * TOPK + rank) * OUTC + 1 + k] = v;
    }

    // replay reset: last decode CTA of each batch clears that batch's flag
    __syncthreads();
    if (tid == 0) {
        int t = atomicAdd(&g_dcnt[b * 32], 1);
        if (t == DGRP - 1) {
            g_dcnt[b * 32] = 0;
            ((volatile int*)g_ready)[b] = 0;
        }
    }
}

extern "C" void kernel_launch(void* const* d_in, const int* in_sizes, int n_in,
                              void* d_out, int out_size)
{
    const float* scores  = (const float*)d_in[0];  // (32,18,64,64)
    const float* bbox    = (const float*)d_in[1];  // (32,576,64,64)
    const float* im_info = (const float*)d_in[2];  // (32,3)
    float* out = (float*)d_out;                    // (32,300,66)

    topk_kernel<<<dim3(SLICES, BATCH), 1024>>>(scores, out);

    // PDL: decode launches as soon as all topk CTAs have signalled
    // launch_dependents (i.e., compaction published); per-batch flags gate
    // the actual data dependency.
    cudaLaunchConfig_t cfg = {};
    cfg.gridDim  = dim3(DGRP, BATCH);
    cfg.blockDim = dim3(512);
    cfg.dynamicSmemBytes = 0;
    cfg.stream = 0;
    cudaLaunchAttribute attr[1];
    attr[0].id = cudaLaunchAttributeProgrammaticStreamSerialization;
    attr[0].val.programmaticStreamSerializationAllowed = 1;
    cfg.attrs = attr;
    cfg.numAttrs = 1;
    cudaLaunchKernelEx(&cfg, decode_kernel, bbox, im_info, out);
}

// round 17
// speedup vs baseline: 1.4472x; 1.0903x over previous
#include <cuda_runtime.h>
#include <cstdint>

#define BATCH   32
#define NA      9
#define HW      4096
#define NPROP   (HW*NA)          // 36864
#define NVEC    (NPROP/4)        // 9216 float4 per batch
#define TOPK    300
#define OUTC    66
#define CAP     2048
#define LCAP    1024             // per-CTA staging (expect ~115)
#define SLICES  4                // compact CTAs per batch

// key threshold for score >= 2.25f (~450 candidates/batch expected, 7σ > 300)
#define THR_FAST 0xC0100000u

// Anchor (w,h) table; centers are always (8+16*gx, 8+16*gy)
__constant__ float c_aw[9] = {92.f,184.f,368.f,64.f,128.f,256.f,44.f,88.f,176.f};
__constant__ float c_ah[9] = {48.f,96.f,192.f,64.f,128.f,256.f,88.f,176.f,352.f};

__device__ int                g_cnt[BATCH * 32];   // candidate counts (128B apart)
__device__ int                g_done[BATCH * 32];  // topk slice tickets
__device__ unsigned long long g_cand[BATCH * CAP];
__device__ unsigned           g_dec[BATCH * TOPK]; // n | (rank<<16), asc n

__device__ __forceinline__ unsigned f2key(float s) {
    unsigned u = __float_as_uint(s);
    return (u & 0x80000000u) ? ~u : (u | 0x80000000u);
}

// ---------------------------------------------------------------------------
// Kernel 1 (PDL primary): compact + elected-last-finisher rank (R12-proven).
// launch_dependents fires after compact publish so decode CTAs pre-schedule;
// their griddepcontrol.wait releases only when this WHOLE grid retires.
// ---------------------------------------------------------------------------
__global__ __launch_bounds__(1024, 1)
void topk_kernel(const float* __restrict__ scores_in, float* __restrict__ out)
{
    __shared__ unsigned long long buf[LCAP];       // 8 KB  (compact staging)
    __shared__ unsigned long long cand[CAP + 16];  // 16.1 KB (rank, padded)
    __shared__ unsigned hist[4096];                // 16 KB (fallback only)
    __shared__ unsigned sel_n[TOPK + 8];           // padded for unroll
    __shared__ unsigned wsum[32], wpre[32];
    __shared__ unsigned s_thr;
    __shared__ int s_cnt, s_base, s_C, s_isrank;

    const int b     = blockIdx.y;
    const int slice = blockIdx.x;
    const int tid   = threadIdx.x;
    const unsigned lane = tid & 31u;
    const int warp  = tid >> 5;

    const float4* sp =
        (const float4*)(scores_in + (size_t)b * 18 * HW + (size_t)NA * HW);

    // ---------------- compact: smem staging, one global RMW ----------------
    if (tid == 0) s_cnt = 0;
    __syncthreads();

    for (int i = slice * 1024 + tid; i < NVEC; i += SLICES * 1024) {
        float4 v = sp[i];
        float vv[4] = {v.x, v.y, v.z, v.w};
        #pragma unroll
        for (int j = 0; j < 4; j++) {
            unsigned k = f2key(vv[j]);
            if (k >= THR_FAST) {
                int idx = 4 * i + j;               // memory order: a*4096 + hw
                int a = idx >> 12, hw = idx & 4095;
                int n = hw * 9 + a;                // jax flat order
                int pos = atomicAdd(&s_cnt, 1);    // smem atomic: cheap
                if (pos < LCAP)
                    buf[pos] = ((unsigned long long)k << 32) | (unsigned)(~n);
            }
        }
    }
    __syncthreads();

    const int cnt = s_cnt;
    if (cnt > LCAP) {
        // staging overflow (benign-impossible): poison count -> exact fallback
        if (tid == 0) atomicAdd(&g_cnt[b * 32], CAP + 1);
    } else {
        if (tid == 0) s_base = atomicAdd(&g_cnt[b * 32], cnt);  // ONE RMW
        __syncthreads();
        for (int i = tid; i < cnt; i += 1024) {
            int pos = s_base + i;
            if (pos < CAP) g_cand[b * CAP + pos] = buf[i];
        }
    }
    __threadfence();                  // publish this CTA's candidate writes
    __syncthreads();
    if (tid == 0) {
        int t = atomicAdd(&g_done[b * 32], 1);
        s_isrank = (t == SLICES - 1); // last finisher ranks this batch
    }
    // Let the dependent decode grid begin scheduling; its wait still blocks
    // until this entire grid completes (full memory visibility, no flags).
    asm volatile("griddepcontrol.launch_dependents;" ::: "memory");
    __syncthreads();
    if (!s_isrank) return;

    // ---------------- rank (elected CTA; all peers already done) ----------
    __threadfence();                  // acquire peers' g_cand writes
    if (tid == 0) s_C = g_cnt[b * 32];
    __syncthreads();
    int C = s_C;
    if (tid == 0) { g_cnt[b * 32] = 0; g_done[b * 32] = 0; }   // replay reset

    if (C >= TOPK && C <= CAP) {
        for (int i = tid; i < C; i += 1024)
            cand[i] = g_cand[b * CAP + i];
    } else {
        // ---- exact fallback: 4096-bin histogram select (1024 threads) ----
        #pragma unroll
        for (int i = tid; i < 4096; i += 1024) hist[i] = 0;
        if (tid == 0) s_cnt = 0;
        __syncthreads();
        #pragma unroll 3
        for (int i = tid; i < NVEC; i += 1024) {
            float4 v = sp[i];
            atomicAdd(&hist[f2key(v.x) >> 20], 1u);
            atomicAdd(&hist[f2key(v.y) >> 20], 1u);
            atomicAdd(&hist[f2key(v.z) >> 20], 1u);
            atomicAdd(&hist[f2key(v.w) >> 20], 1u);
        }
        __syncthreads();
        // suffix scan from the top: thread t owns bins [4095-4t .. 4092-4t]
        const int bhi = 4095 - 4 * tid;
        unsigned h0 = hist[bhi],     h1 = hist[bhi - 1];
        unsigned h2 = hist[bhi - 2], h3 = hist[bhi - 3];
        unsigned s = h0 + h1 + h2 + h3;
        unsigned incl = s;
        #pragma unroll
        for (int o = 1; o < 32; o <<= 1) {
            unsigned v = __shfl_up_sync(0xFFFFFFFFu, incl, o);
            if (lane >= o) incl += v;
        }
        if (lane == 31) wsum[warp] = incl;
        __syncthreads();
        if (warp == 0) {
            unsigned w = wsum[lane];
            unsigned wi = w;
            #pragma unroll
            for (int o = 1; o < 32; o <<= 1) {
                unsigned v = __shfl_up_sync(0xFFFFFFFFu, wi, o);
                if (lane >= o) wi += v;
            }
            wpre[lane] = wi - w;
        }
        __syncthreads();
        {
            unsigned cc = wpre[warp] + (incl - s);   // count above bin bhi
            unsigned hh[4] = {h0, h1, h2, h3};
            #pragma unroll
            for (int j = 0; j < 4; j++) {
                if (cc < TOPK && cc + hh[j] >= TOPK)
                    s_thr = ((unsigned)(bhi - j)) << 20;
                cc += hh[j];
            }
        }
        __syncthreads();
        const unsigned thr = s_thr;
        if (tid == 0) s_cnt = 0;
        __syncthreads();
        #pragma unroll 3
        for (int i = tid; i < NVEC; i += 1024) {
            float4 v = sp[i];
            float vv[4] = {v.x, v.y, v.z, v.w};
            #pragma unroll
            for (int j = 0; j < 4; j++) {
                unsigned k = f2key(vv[j]);
                if (k >= thr) {
                    int idx = 4 * i + j;
                    int a = idx >> 12, hw = idx & 4095;
                    int n = hw * 9 + a;
                    int pos = atomicAdd(&s_cnt, 1);
                    if (pos < CAP)
                        cand[pos] = ((unsigned long long)k << 32) | (unsigned)(~n);
                }
            }
        }
        __syncthreads();
        C = min(s_cnt, CAP);
    }
    // zero-pad so the unrolled rank loop can overrun harmlessly
    if (tid < 16) cand[C + tid] = 0ull;
    __syncthreads();

    // ---- exact rank by counting, 16x unrolled (independent LDS in flight)
    for (int i = tid; i < C; i += 1024) {
        const unsigned long long me = cand[i];
        int r = 0;
        for (int j = 0; j < C; j += 16) {
            #pragma unroll
            for (int u = 0; u < 16; u++)
                r += (cand[j + u] > me);           // broadcast reads
        }
        if (r < TOPK) {
            unsigned n = (unsigned)(~(unsigned)me);
            sel_n[r] = n;
            unsigned k32 = (unsigned)(me >> 32);
            unsigned u = (k32 & 0x80000000u) ? (k32 & 0x7FFFFFFFu) : ~k32;
            size_t row = ((size_t)b * TOPK + r) * OUTC;
            out[row + 0] = (float)b;
            out[row + OUTC - 1] = __uint_as_float(u);
        }
    }
    if (tid < 8) sel_n[TOPK + tid] = 0xFFFFFFFFu;  // pad: never counts as less
    __syncthreads();

    // decode feed in ascending flat-index order (gather locality), unrolled
    if (tid < TOPK) {
        unsigned n = sel_n[tid];
        int o = 0;
        for (int j = 0; j < TOPK + 4; j += 4) {
            #pragma unroll
            for (int u = 0; u < 4; u++)
                o += (sel_n[j + u] < n);
        }
        g_dec[b * TOPK + o] = n | ((unsigned)tid << 16);
    }
}

// ---------------------------------------------------------------------------
// Kernel 2 (PDL secondary): decode — R12-proven body. griddepcontrol.wait
// blocks until the primary grid fully retires (memory-visible), then runs
// with the machine to itself.
// ---------------------------------------------------------------------------
__global__ __launch_bounds__(512)
void decode_kernel(const float* __restrict__ bbox,
                   const float* __restrict__ im_info,
                   float* __restrict__ out)
{
    asm volatile("griddepcontrol.wait;" ::: "memory");

    const int tid = threadIdx.x;
    const int j = blockIdx.x * 8 + (tid >> 6);
    const int b = blockIdx.y;
    const int k = tid & 63;
    if (j >= TOPK) return;                     // 64-thread groups: warp-uniform

    const unsigned packed = g_dec[b * TOPK + j];
    const int n    = packed & 0xFFFFu;
    const int rank = packed >> 16;

    const int a  = n % 9;
    const int hw = n / 9;
    const float w  = c_aw[a];
    const float h  = c_ah[a];
    const float cx = 8.0f + 16.0f * (float)(hw & 63);
    const float cy = 8.0f + 16.0f * (float)(hw >> 6);

    const float d = __ldcs(&bbox[((size_t)b * 576 + (size_t)a * 64 + k) * HW + hw]);

    const unsigned base = (tid & 31u) & ~3u;
    const float d0 = __shfl_sync(0xFFFFFFFFu, d, base + 0);
    const float d1 = __shfl_sync(0xFFFFFFFFu, d, base + 1);
    const float d2 = __shfl_sync(0xFFFFFFFFu, d, base + 2);
    const float d3 = __shfl_sync(0xFFFFFFFFu, d, base + 3);

    const float xmax = im_info[b * 3 + 1] - 1.0f;
    const float ymax = im_info[b * 3 + 0] - 1.0f;

    const float pcx = d0 * w + cx;
    const float pcy = d1 * h + cy;
    const float pw  = expf(d2) * w;
    const float ph  = expf(d3) * h;

    float v;
    switch (k & 3) {
        case 0: v = fminf(fmaxf(pcx - 0.5f * pw, 0.0f), xmax); break;
        case 1: v = fminf(fmaxf(pcy - 0.5f * ph, 0.0f), ymax); break;
        case 2: v = fminf(fmaxf(pcx + 0.5f * pw, 0.0f), xmax); break;
        default: v = fminf(fmaxf(pcy + 0.5f * ph, 0.0f), ymax); break;
    }

    out[((size_t)b * TOPK + rank) * OUTC + 1 + k] = v;
}

extern "C" void kernel_launch(void* const* d_in, const int* in_sizes, int n_in,
                              void* d_out, int out_size)
{
    const float* scores  = (const float*)d_in[0];  // (32,18,64,64)
    const float* bbox    = (const float*)d_in[1];  // (32,576,64,64)
    const float* im_info = (const float*)d_in[2];  // (32,3)
    float* out = (float*)d_out;                    // (32,300,66)

    topk_kernel<<<dim3(SLICES, BATCH), 1024>>>(scores, out);

    // PDL: decode pre-schedules during topk's rank tail; its wait releases
    // the moment the primary grid retires.
    cudaLaunchConfig_t cfg = {};
    cfg.gridDim  = dim3((TOPK + 7) / 8, BATCH);
    cfg.blockDim = dim3(512);
    cfg.dynamicSmemBytes = 0;
    cfg.stream = 0;
    cudaLaunchAttribute attr[1];
    attr[0].id = cudaLaunchAttributeProgrammaticStreamSerialization;
    attr[0].val.programmaticStreamSerializationAllowed = 1;
    cfg.attrs = attr;
    cfg.numAttrs = 1;
    cudaLaunchKernelEx(&cfg, decode_kernel, bbox, im_info, out);
}